// round 4
// baseline (speedup 1.0000x reference)
#include <cuda_runtime.h>

// NeuralODE: encoder -> 99 RK4 steps -> decoder at every timestep.
// One element per LANE-PAIR (lane l and l^16 in the same warp): each lane
// computes 25 of the 50 hidden units, partial k combined via shfl_xor(16).
// Doubles warp count vs 2-elem/thread version (latency was the binder:
// occ 8.4%, issue 53%) while keeping per-element LDS traffic amortized.

#define HID 50
#define LAT 16

typedef unsigned long long u64;

__device__ __forceinline__ u64 pk2(float a, float b) {
    u64 v; asm("mov.b64 %0, {%1,%2};" : "=l"(v) : "f"(a), "f"(b)); return v;
}
__device__ __forceinline__ float2 up2(u64 v) {
    float2 r; asm("mov.b64 {%0,%1}, %2;" : "=f"(r.x), "=f"(r.y) : "l"(v)); return r;
}
__device__ __forceinline__ u64 ffma2(u64 a, u64 b, u64 c) {
    u64 d; asm("fma.rn.f32x2 %0, %1, %2, %3;" : "=l"(d) : "l"(a), "l"(b), "l"(c)); return d;
}
__device__ __forceinline__ u64 fmul2(u64 a, u64 b) {
    u64 d; asm("mul.rn.f32x2 %0, %1, %2;" : "=l"(d) : "l"(a), "l"(b)); return d;
}
__device__ __forceinline__ u64 fadd2(u64 a, u64 b) {
    u64 d; asm("add.rn.f32x2 %0, %1, %2;" : "=l"(d) : "l"(a), "l"(b)); return d;
}

// tanh(x) = 1 - 2/(1+e^{2x});  EX2+RCP based, ~1e-6 rel err, saturates correctly.
__device__ __forceinline__ float tanh_fast(float x) {
    float e = __expf(2.0f * x);
    return 1.0f - __fdividef(2.0f, e + 1.0f);
}

struct __align__(16) SW {
    float wo1t[HID * LAT];  // wo1t[i*16+k] = Wo1[k][i]
    float wo2 [HID * LAT];  // Wo2[i][j], row-major
    float we2 [HID * LAT];  // We2[i][k], row-major
    float wd1t[HID * LAT];  // wd1t[i*16+k] = Wd1[k][i]
    float bo2[LAT];
    float be2[LAT];
    float bo1[HID];
    float be1[HID];
    float bd1[HID];
    float we1a[HID];        // We1[0][i]
    float we1b[HID];        // We1[1][i]
    float wd2[HID];
    float dt[256];
    float bd2;
};

// dot of 16-dim packed z with a contiguous 16-float weight row (shared mem)
__device__ __forceinline__ float dot16(const u64 zp[8], const float* __restrict__ row) {
    const ulonglong2* w = (const ulonglong2*)row;
    ulonglong2 w0 = w[0], w1 = w[1], w2 = w[2], w3 = w[3];
    u64 a0 = fmul2(zp[0], w0.x);
    u64 a1 = fmul2(zp[1], w0.y);
    a0 = ffma2(zp[2], w1.x, a0);
    a1 = ffma2(zp[3], w1.y, a1);
    a0 = ffma2(zp[4], w2.x, a0);
    a1 = ffma2(zp[5], w2.y, a1);
    a0 = ffma2(zp[6], w3.x, a0);
    a1 = ffma2(zp[7], w3.y, a1);
    float2 p = up2(fadd2(a0, a1));
    return p.x + p.y;
}

// Partial f over hidden units [i0, i0+25), then combine across the lane pair.
// k = tanh(z@Wo1 + bo1) @ Wo2 + bo2  (z, k packed as 8 f32x2)
__device__ __forceinline__ void ode_f(const u64 z[8], u64 k[8], const SW& s,
                                      int i0, int half) {
    const u64* bo2p = (const u64*)s.bo2;
#pragma unroll
    for (int j = 0; j < 8; j++) k[j] = half ? 0ull : bo2p[j];
#pragma unroll 5
    for (int ii = 0; ii < HID / 2; ii++) {
        int i = i0 + ii;
        float h = tanh_fast(dot16(z, s.wo1t + i * LAT) + s.bo1[i]);
        u64 h2 = pk2(h, h);
        const ulonglong2* w = (const ulonglong2*)(s.wo2 + i * LAT);
#pragma unroll
        for (int j = 0; j < 4; j++) {
            ulonglong2 ww = w[j];
            k[2 * j]     = ffma2(h2, ww.x, k[2 * j]);
            k[2 * j + 1] = ffma2(h2, ww.y, k[2 * j + 1]);
        }
    }
    // combine partial k across lane pair (lane ^ 16)
#pragma unroll
    for (int j = 0; j < 8; j++) {
        u64 o = __shfl_xor_sync(0xffffffffu, k[j], 16);
        k[j] = fadd2(k[j], o);
    }
}

// Partial decode over hidden units [i0, i0+25), combined across lane pair.
__device__ __forceinline__ float decode(const u64 z[8], const SW& s,
                                        int i0, int half) {
    float y = half ? 0.0f : s.bd2;
#pragma unroll 5
    for (int ii = 0; ii < HID / 2; ii++) {
        int i = i0 + ii;
        float h = fmaxf(dot16(z, s.wd1t + i * LAT) + s.bd1[i], 0.0f);
        y = fmaf(h, s.wd2[i], y);
    }
    y += __shfl_xor_sync(0xffffffffu, y, 16);
    return y;
}

__global__ void __launch_bounds__(64)
node_kernel(const float* __restrict__ x0, const float* __restrict__ t,
            const float* __restrict__ We1, const float* __restrict__ be1,
            const float* __restrict__ We2, const float* __restrict__ be2,
            const float* __restrict__ Wo1, const float* __restrict__ bo1,
            const float* __restrict__ Wo2, const float* __restrict__ bo2,
            const float* __restrict__ Wd1, const float* __restrict__ bd1,
            const float* __restrict__ Wd2, const float* __restrict__ bd2,
            float* __restrict__ out, int Bn, int Tn) {
    __shared__ SW s;
    int tid = threadIdx.x;

    for (int idx = tid; idx < HID * LAT; idx += blockDim.x) {
        int i = idx >> 4, k = idx & 15;
        s.wo1t[idx] = Wo1[k * HID + i];
        s.wd1t[idx] = Wd1[k * HID + i];
        s.wo2[idx]  = Wo2[idx];
        s.we2[idx]  = We2[idx];
    }
    for (int idx = tid; idx < HID; idx += blockDim.x) {
        s.bo1[idx]  = bo1[idx];
        s.be1[idx]  = be1[idx];
        s.bd1[idx]  = bd1[idx];
        s.we1a[idx] = We1[idx];
        s.we1b[idx] = We1[HID + idx];
        s.wd2[idx]  = Wd2[idx];
    }
    for (int idx = tid; idx < LAT; idx += blockDim.x) {
        s.bo2[idx] = bo2[idx];
        s.be2[idx] = be2[idx];
    }
    for (int idx = tid; idx < Tn - 1 && idx < 256; idx += blockDim.x)
        s.dt[idx] = t[idx + 1] - t[idx];
    if (tid == 0) s.bd2 = bd2[0];
    __syncthreads();

    int warp = tid >> 5, lane = tid & 31;
    int half = lane >> 4;          // which 25 hidden units this lane owns
    int i0   = half * (HID / 2);
    int b = blockIdx.x * 32 + warp * 16 + (lane & 15);
    bool valid = (b < Bn);
    int bc = valid ? b : (Bn - 1);   // clamp; no early return (shfl pairs)

    // ---------- Encoder (tiny, one-time): full 50-unit loop per thread ----
    float2 x = ((const float2*)x0)[bc];
    u64 z[8];
    {
        const u64* be2p = (const u64*)s.be2;
#pragma unroll
        for (int j = 0; j < 8; j++) z[j] = be2p[j];
#pragma unroll 5
        for (int i = 0; i < HID; i++) {
            float h = fmaf(x.y, s.we1b[i], fmaf(x.x, s.we1a[i], s.be1[i]));
            h = fmaxf(h, 0.0f);
            u64 h2 = pk2(h, h);
            const ulonglong2* w = (const ulonglong2*)(s.we2 + i * LAT);
#pragma unroll
            for (int j = 0; j < 4; j++) {
                ulonglong2 ww = w[j];
                z[2 * j]     = ffma2(h2, ww.x, z[2 * j]);
                z[2 * j + 1] = ffma2(h2, ww.y, z[2 * j + 1]);
            }
        }
    }

    {
        float y = decode(z, s, i0, half);
        if (valid && half == 0) out[b] = y;
    }

    // ---------- RK4 time stepping (stages fully unrolled) ----------
    for (int st = 0; st < Tn - 1; ++st) {
        float dt = s.dt[st];
        float h6 = dt * (1.0f / 6.0f);
        float h3 = dt * (1.0f / 3.0f);
        float hf = dt * 0.5f;
        u64 c6 = pk2(h6, h6), c3 = pk2(h3, h3), c2 = pk2(hf, hf), c1 = pk2(dt, dt);

        u64 zn[8], zt[8], kk[8];

        // stage 1
        ode_f(z, kk, s, i0, half);
#pragma unroll
        for (int j = 0; j < 8; j++) {
            zn[j] = ffma2(c6, kk[j], z[j]);
            zt[j] = ffma2(c2, kk[j], z[j]);
        }
        // stage 2
        ode_f(zt, kk, s, i0, half);
#pragma unroll
        for (int j = 0; j < 8; j++) {
            zn[j] = ffma2(c3, kk[j], zn[j]);
            zt[j] = ffma2(c2, kk[j], z[j]);
        }
        // stage 3
        ode_f(zt, kk, s, i0, half);
#pragma unroll
        for (int j = 0; j < 8; j++) {
            zn[j] = ffma2(c3, kk[j], zn[j]);
            zt[j] = ffma2(c1, kk[j], z[j]);
        }
        // stage 4
        ode_f(zt, kk, s, i0, half);
#pragma unroll
        for (int j = 0; j < 8; j++)
            z[j] = ffma2(c6, kk[j], zn[j]);

        float y = decode(z, s, i0, half);
        if (valid && half == 0) out[(size_t)(st + 1) * Bn + b] = y;
    }
}

extern "C" void kernel_launch(void* const* d_in, const int* in_sizes, int n_in,
                              void* d_out, int out_size) {
    const float* x0  = (const float*)d_in[0];
    const float* t   = (const float*)d_in[1];
    const float* We1 = (const float*)d_in[2];
    const float* be1 = (const float*)d_in[3];
    const float* We2 = (const float*)d_in[4];
    const float* be2 = (const float*)d_in[5];
    const float* Wo1 = (const float*)d_in[6];
    const float* bo1 = (const float*)d_in[7];
    const float* Wo2 = (const float*)d_in[8];
    const float* bo2 = (const float*)d_in[9];
    const float* Wd1 = (const float*)d_in[10];
    const float* bd1 = (const float*)d_in[11];
    const float* Wd2 = (const float*)d_in[12];
    const float* bd2 = (const float*)d_in[13];

    int Bn = in_sizes[0] / 2;   // x0 is (B, 2)
    int Tn = in_sizes[1];       // t is (T,)

    int threads = 64;                    // 2 warps; 32 elements per block
    int blocks = (Bn + 31) / 32;         // 2 threads per element
    node_kernel<<<blocks, threads>>>(x0, t, We1, be1, We2, be2, Wo1, bo1,
                                     Wo2, bo2, Wd1, bd1, Wd2, bd2,
                                     (float*)d_out, Bn, Tn);
}